// round 2
// baseline (speedup 1.0000x reference)
#include <cuda_runtime.h>
#include <math.h>

// ---------------- static problem config ----------------
#define NTOK   8192
#define HDIM   1024
#define CH     2048       // 2*H context hidden
#define CTXD   64
#define POSD   32
#define DGDIM  1120
#define HIDDIM 3072
#define NEXP   8
#define NKENT  16384      // NTOK * K
#define CAP    2048
#define BATCH  4
#define SEQ    2048

// output layout (flat float32, tuple order)
#define OFF_IDX   0
#define OFF_SCORE 16384
#define OFF_MASK  32768
#define OFF_POS   49152
#define OFF_OVER  65536
#define OFF_CNT   73728
#define OFF_AUX   73736
#define OFF_NEXT  73737

// ---------------- scratch (device globals, no allocation) ----------------
__device__ float g_hidden[NTOK * CH];
__device__ float g_ctx[NTOK * CTXD];
__device__ float g_gi[NTOK * DGDIM];
__device__ float g_s1[NTOK * HIDDIM];
__device__ float g_h1[NTOK * HIDDIM];
__device__ float g_h[NTOK * DGDIM];
__device__ float g_scores[NTOK * NEXP];
__device__ unsigned long long g_keys[NKENT];
__device__ int g_expert_flat[NKENT];
__device__ unsigned char g_assigned[NKENT];
__device__ int g_cnt[NEXP];

// ---------------- SGEMM: C[M,N] = epi(A[M,K] @ B[K,N]) ----------------
// EPI: 0 = none, 1 = +bias, 2 = gelu(+bias), 3 = silu(aux)*acc, 4 = acc+aux
template <int EPI>
__global__ __launch_bounds__(256)
void sgemm_kernel(int M, int N, int K,
                  const float* __restrict__ A, const float* __restrict__ B,
                  float* __restrict__ C,
                  const float* __restrict__ bias, const float* __restrict__ aux)
{
    constexpr int BM = 128, BN = 128, BK = 16, TM = 8, TN = 8;
    constexpr int THREADS = (BM / TM) * (BN / TN);   // 256
    __shared__ float As[BK][BM];
    __shared__ float Bs[BK][BN];

    const int bm = blockIdx.y * BM;
    const int bn = blockIdx.x * BN;
    const int tid = threadIdx.x;
    const int tcol = tid % (BN / TN);   // 0..15
    const int trow = tid / (BN / TN);   // 0..15

    float acc[TM][TN];
#pragma unroll
    for (int i = 0; i < TM; i++)
#pragma unroll
        for (int j = 0; j < TN; j++) acc[i][j] = 0.f;

    constexpr int AV = BM * BK / 4;   // float4 count in A tile
    constexpr int BV = BK * BN / 4;

    for (int k0 = 0; k0 < K; k0 += BK) {
        // A tile (M,K row-major; M multiple of BM, K multiple of BK)
#pragma unroll
        for (int v = tid; v < AV; v += THREADS) {
            int r = v / (BK / 4);
            int c4 = v % (BK / 4);
            float4 t = *(const float4*)&A[(long)(bm + r) * K + k0 + c4 * 4];
            As[c4 * 4 + 0][r] = t.x;
            As[c4 * 4 + 1][r] = t.y;
            As[c4 * 4 + 2][r] = t.z;
            As[c4 * 4 + 3][r] = t.w;
        }
        // B tile (K,N row-major) — guard N (N always multiple of 4)
#pragma unroll
        for (int v = tid; v < BV; v += THREADS) {
            int r = v / (BN / 4);
            int c4 = v % (BN / 4);
            int col = bn + c4 * 4;
            float4 t = make_float4(0.f, 0.f, 0.f, 0.f);
            if (col < N) t = *(const float4*)&B[(long)(k0 + r) * N + col];
            *(float4*)&Bs[r][c4 * 4] = t;
        }
        __syncthreads();
#pragma unroll
        for (int kk = 0; kk < BK; kk++) {
            float a[TM], b[TN];
#pragma unroll
            for (int i = 0; i < TM; i++) a[i] = As[kk][trow * TM + i];
#pragma unroll
            for (int j = 0; j < TN; j++) b[j] = Bs[kk][tcol * TN + j];
#pragma unroll
            for (int i = 0; i < TM; i++)
#pragma unroll
                for (int j = 0; j < TN; j++) acc[i][j] += a[i] * b[j];
        }
        __syncthreads();
    }

#pragma unroll
    for (int i = 0; i < TM; i++) {
        int row = bm + trow * TM + i;
#pragma unroll
        for (int j = 0; j < TN; j++) {
            int col = bn + tcol * TN + j;
            if (col >= N) continue;
            float v = acc[i][j];
            if (EPI == 1) v += bias[col];
            else if (EPI == 2) {
                v += bias[col];
                v = 0.5f * v * (1.0f + erff(v * 0.70710678118654752f));
            } else if (EPI == 3) {
                float s = aux[(long)row * N + col];
                v = (s / (1.0f + expf(-s))) * v;
            } else if (EPI == 4) {
                v += aux[(long)row * N + col];
            }
            C[(long)row * N + col] = v;
        }
    }
}

// ---------------- build gi = rmsnorm(concat(x, ctx, pos_emb)) ----------------
__global__ __launch_bounds__(256)
void build_gi_kernel(const float* __restrict__ x,
                     const int* __restrict__ positions,
                     const float* __restrict__ pos_table,
                     const float* __restrict__ normw)
{
    int row = blockIdx.x;
    __shared__ float vec[DGDIM];
    __shared__ float red[256];
    int tid = threadIdx.x;
    const float* xr = x + (long)row * HDIM;
    const float* pr = pos_table + (long)positions[row] * POSD;
    float ss = 0.f;
    for (int i = tid; i < DGDIM; i += 256) {
        float v;
        if (i < HDIM) v = xr[i];
        else if (i < HDIM + CTXD) v = g_ctx[(long)row * CTXD + (i - HDIM)];
        else v = pr[i - HDIM - CTXD];
        vec[i] = v;
        ss += v * v;
    }
    red[tid] = ss;
    __syncthreads();
    for (int s = 128; s > 0; s >>= 1) {
        if (tid < s) red[tid] += red[tid + s];
        __syncthreads();
    }
    float scale = rsqrtf(red[0] / (float)DGDIM + 1e-6f);
    for (int i = tid; i < DGDIM; i += 256)
        g_gi[(long)row * DGDIM + i] = vec[i] * scale * normw[i];
}

// ---------------- router: logits -> softmax -> top2 -> sort keys ----------------
__global__ __launch_bounds__(256)
void router_kernel(const float* __restrict__ projw,
                   const float* __restrict__ tptr,
                   float* __restrict__ out)
{
    int row = blockIdx.x * 8 + (threadIdx.x >> 5);
    int lane = threadIdx.x & 31;
    if (row >= NTOK) return;
    const float* h = g_h + (long)row * DGDIM;
    float acc[NEXP];
#pragma unroll
    for (int e = 0; e < NEXP; e++) acc[e] = 0.f;
    for (int i = lane; i < DGDIM; i += 32) {
        float hv = h[i];
        const float4* p = (const float4*)(projw + (long)i * NEXP);
        float4 w0 = p[0], w1 = p[1];
        acc[0] += hv * w0.x; acc[1] += hv * w0.y;
        acc[2] += hv * w0.z; acc[3] += hv * w0.w;
        acc[4] += hv * w1.x; acc[5] += hv * w1.y;
        acc[6] += hv * w1.z; acc[7] += hv * w1.w;
    }
#pragma unroll
    for (int e = 0; e < NEXP; e++)
#pragma unroll
        for (int o = 16; o > 0; o >>= 1)
            acc[e] += __shfl_xor_sync(0xFFFFFFFFu, acc[e], o);

    if (lane == 0) {
        float t = fmaxf(*tptr, 0.3f);
        float l[NEXP], m = -1e30f;
#pragma unroll
        for (int e = 0; e < NEXP; e++) { l[e] = acc[e] / t; m = fmaxf(m, l[e]); }
        float s = 0.f;
#pragma unroll
        for (int e = 0; e < NEXP; e++) { l[e] = expf(l[e] - m); s += l[e]; }
        float inv = 1.0f / s;
#pragma unroll
        for (int e = 0; e < NEXP; e++) {
            l[e] *= inv;
            g_scores[(long)row * NEXP + e] = l[e];
        }
        // top-2, ties -> lowest index (strict >)
        int i1 = 0;
#pragma unroll
        for (int e = 1; e < NEXP; e++) if (l[e] > l[i1]) i1 = e;
        int i2 = (i1 == 0) ? 1 : 0;
#pragma unroll
        for (int e = 0; e < NEXP; e++)
            if (e != i1 && e != i2 && l[e] > l[i2]) i2 = e;

        int idx2[2] = {i1, i2};
#pragma unroll
        for (int k = 0; k < 2; k++) {
            int fi = row * 2 + k;
            float w = l[idx2[k]];
            out[OFF_IDX + fi] = (float)idx2[k];
            out[OFF_SCORE + fi] = w;
            g_expert_flat[fi] = idx2[k];
            unsigned int bits = __float_as_uint(w);   // w > 0 => monotonic
            g_keys[fi] = ((unsigned long long)(0xFFFFFFFFu - bits) << 32) |
                         (unsigned long long)(unsigned int)fi;
        }
    }
}

// ---------------- single-block bitonic sort + capacity dispatch ----------------
__global__ __launch_bounds__(1024, 1)
void sort_dispatch_kernel(float* __restrict__ out)
{
    extern __shared__ unsigned long long keys[];   // NKENT entries = 128 KB
    const int tid = threadIdx.x;                    // 1024 threads
    for (int i = tid; i < NKENT; i += 1024) keys[i] = g_keys[i];
    __syncthreads();

    // ascending sort: key = (~bits(w), idx) => weight desc, index asc (stable)
    for (int k = 2; k <= NKENT; k <<= 1) {
        for (int j = k >> 1; j > 0; j >>= 1) {
            for (int i = tid; i < NKENT; i += 1024) {
                int ixj = i ^ j;
                if (ixj > i) {
                    bool up = ((i & k) == 0);
                    unsigned long long a = keys[i], b = keys[ixj];
                    if ((a > b) == up) { keys[i] = b; keys[ixj] = a; }
                }
            }
            __syncthreads();
        }
    }

    // per-expert ranking: warp e scans sorted order, ballot-prefix counts
    int warp = tid >> 5, lane = tid & 31;
    if (warp < NEXP) {
        int c = 0;
        for (int base = 0; base < NKENT; base += 32) {
            unsigned long long kk = keys[base + lane];
            int idx = (int)(kk & 0xFFFFFFFFu);
            int e = g_expert_flat[idx];
            unsigned int mask = __ballot_sync(0xFFFFFFFFu, e == warp);
            if (e == warp) {
                int rank = c + __popc(mask & ((1u << lane) - 1u));
                bool ok = rank < CAP;
                g_assigned[idx] = ok ? 1 : 0;
                out[OFF_MASK + idx] = ok ? 1.0f : 0.0f;
                out[OFF_POS + idx] = ok ? (float)rank : 0.0f;
            }
            c += __popc(mask);
        }
        if (lane == 0) {
            int cnt = c < CAP ? c : CAP;
            g_cnt[warp] = cnt;
            out[OFF_CNT + warp] = (float)cnt;
        }
    }
    __syncthreads();
    for (int n = tid; n < NTOK; n += 1024)
        out[OFF_OVER + n] =
            (g_assigned[2 * n] | g_assigned[2 * n + 1]) ? 0.0f : 1.0f;
}

// ---------------- next_context mean ----------------
__global__ __launch_bounds__(256)
void next_ctx_kernel(const int* __restrict__ positions,
                     const float* __restrict__ pos_table,
                     float* __restrict__ out)
{
    int j = blockIdx.x % (CTXD + POSD);
    int b = blockIdx.x / (CTXD + POSD);
    __shared__ float red[256];
    float s = 0.f;
    for (int t = threadIdx.x; t < SEQ; t += 256) {
        int row = b * SEQ + t;
        float v = (j < CTXD) ? g_ctx[(long)row * CTXD + j]
                             : pos_table[(long)positions[row] * POSD + (j - CTXD)];
        s += v;
    }
    red[threadIdx.x] = s;
    __syncthreads();
    for (int st = 128; st > 0; st >>= 1) {
        if (threadIdx.x < st) red[threadIdx.x] += red[threadIdx.x + st];
        __syncthreads();
    }
    if (threadIdx.x == 0)
        out[OFF_NEXT + b * (CTXD + POSD) + j] = red[0] / (float)SEQ;
}

// ---------------- aux loss ----------------
__global__ __launch_bounds__(256)
void aux_kernel(float* __restrict__ out)
{
    __shared__ float sh[256 * NEXP];
    int tid = threadIdx.x;
    float acc[NEXP];
#pragma unroll
    for (int e = 0; e < NEXP; e++) acc[e] = 0.f;
    for (int r = tid; r < NTOK; r += 256)
#pragma unroll
        for (int e = 0; e < NEXP; e++) acc[e] += g_scores[(long)r * NEXP + e];
#pragma unroll
    for (int e = 0; e < NEXP; e++) sh[tid * NEXP + e] = acc[e];
    __syncthreads();
    for (int s = 128; s > 0; s >>= 1) {
        if (tid < s)
#pragma unroll
            for (int e = 0; e < NEXP; e++)
                sh[tid * NEXP + e] += sh[(tid + s) * NEXP + e];
        __syncthreads();
    }
    if (tid == 0) {
        float a = 0.f;
        for (int e = 0; e < NEXP; e++) {
            float me = sh[e] / (float)NTOK;
            float ce = (float)g_cnt[e] / (float)NTOK;
            a += me * ce;
        }
        out[OFF_AUX] = 0.01f * (float)NEXP * a;
    }
}

// ---------------- launch ----------------
extern "C" void kernel_launch(void* const* d_in, const int* in_sizes, int n_in,
                              void* d_out, int out_size)
{
    const float* x        = (const float*)d_in[0];
    const int*   positions= (const int*)d_in[1];
    const float* w_c1     = (const float*)d_in[2];
    const float* b_c1     = (const float*)d_in[3];
    const float* w_c2     = (const float*)d_in[4];
    const float* b_c2     = (const float*)d_in[5];
    const float* norm_w   = (const float*)d_in[6];
    const float* mlp_w1   = (const float*)d_in[7];
    const float* mlp_w3   = (const float*)d_in[8];
    const float* mlp_w2   = (const float*)d_in[9];
    const float* proj_w   = (const float*)d_in[10];
    const float* pos_table= (const float*)d_in[11];
    const float* temp     = (const float*)d_in[12];
    float* out = (float*)d_out;

    float *p_hidden, *p_ctx, *p_gi, *p_s1, *p_h1, *p_h;
    cudaGetSymbolAddress((void**)&p_hidden, g_hidden);
    cudaGetSymbolAddress((void**)&p_ctx,    g_ctx);
    cudaGetSymbolAddress((void**)&p_gi,     g_gi);
    cudaGetSymbolAddress((void**)&p_s1,     g_s1);
    cudaGetSymbolAddress((void**)&p_h1,     g_h1);
    cudaGetSymbolAddress((void**)&p_h,      g_h);

    // 1. hidden = gelu(x @ w_c1 + b_c1)    [8192, 2048]
    sgemm_kernel<2><<<dim3(CH / 128, NTOK / 128), 256>>>(
        NTOK, CH, HDIM, x, w_c1, p_hidden, b_c1, nullptr);
    // 2. ctx = hidden @ w_c2 + b_c2        [8192, 64]
    sgemm_kernel<1><<<dim3(1, NTOK / 128), 256>>>(
        NTOK, CTXD, CH, p_hidden, w_c2, p_ctx, b_c2, nullptr);
    // 3. gi = rmsnorm(concat(x, ctx, pos_emb))
    build_gi_kernel<<<NTOK, 256>>>(x, positions, pos_table, norm_w);
    // 4. s1 = gi @ mlp_w1                  [8192, 3072]
    sgemm_kernel<0><<<dim3(HIDDIM / 128, NTOK / 128), 256>>>(
        NTOK, HIDDIM, DGDIM, p_gi, mlp_w1, p_s1, nullptr, nullptr);
    // 5. h1 = silu(s1) * (gi @ mlp_w3)
    sgemm_kernel<3><<<dim3(HIDDIM / 128, NTOK / 128), 256>>>(
        NTOK, HIDDIM, DGDIM, p_gi, mlp_w3, p_h1, nullptr, p_s1);
    // 6. h = h1 @ mlp_w2 + gi              [8192, 1120]
    sgemm_kernel<4><<<dim3((DGDIM + 127) / 128, NTOK / 128), 256>>>(
        NTOK, DGDIM, HIDDIM, p_h1, mlp_w2, p_h, nullptr, p_gi);
    // 7. router: logits, softmax, top-2, sort keys
    router_kernel<<<NTOK / 8, 256>>>(proj_w, temp, out);
    // 8. sort + capacity dispatch (128 KB dynamic smem)
    cudaFuncSetAttribute(sort_dispatch_kernel,
                         cudaFuncAttributeMaxDynamicSharedMemorySize,
                         NKENT * (int)sizeof(unsigned long long));
    sort_dispatch_kernel<<<1, 1024, NKENT * sizeof(unsigned long long)>>>(out);
    // 9. next_context
    next_ctx_kernel<<<BATCH * (CTXD + POSD), 256>>>(positions, pos_table, out);
    // 10. aux loss
    aux_kernel<<<1, 256>>>(out);
}

// round 4
// speedup vs baseline: 1.8092x; 1.8092x over previous
#include <cuda_runtime.h>
#include <cuda_bf16.h>
#include <math.h>
#include <stdint.h>

// ---------------- static problem config ----------------
#define NTOK   8192
#define HDIM   1024
#define CH     2048
#define CTXD   64
#define POSD   32
#define DGDIM  1120
#define HIDDIM 3072
#define NEXP   8
#define NKENT  16384
#define CAP    2048
#define BATCH  4
#define SEQ    2048

// expanded-K (bf16x2 split, 3 products) widths
#define KP1   (3*HDIM)    // 3072
#define KP2   (3*CH)      // 6144
#define KP45  (3*DGDIM)   // 3360
#define KP6   (3*HIDDIM)  // 9216
#define NPAD2 128         // GEMM2 N padded (real 64)
#define NPAD6 1152        // GEMM6 N padded (real 1120)

// output layout (flat float32, tuple order)
#define OFF_IDX   0
#define OFF_SCORE 16384
#define OFF_MASK  32768
#define OFF_POS   49152
#define OFF_OVER  65536
#define OFF_CNT   73728
#define OFF_AUX   73736
#define OFF_NEXT  73737

// ---------------- scratch (device globals, no allocation) ----------------
__device__ float g_hidden[NTOK * CH];
__device__ float g_ctx[NTOK * CTXD];
__device__ float g_gi[NTOK * DGDIM];
__device__ float g_s1[NTOK * HIDDIM];
__device__ float g_h1[NTOK * HIDDIM];
__device__ float g_h[NTOK * DGDIM];
__device__ float g_scores[NTOK * NEXP];
__device__ unsigned long long g_keys[NKENT];
__device__ int g_expert_flat[NKENT];
__device__ unsigned char g_assigned[NKENT];
__device__ int g_cnt[NEXP];

// bf16x2-split expanded operands (A planes: [P0,P0,P1]; B planes: [P0,P1,P0])
__device__ __align__(256) __nv_bfloat16 g_ax  [NTOK * KP1];
__device__ __align__(256) __nv_bfloat16 g_ah  [NTOK * KP2];
__device__ __align__(256) __nv_bfloat16 g_agi [NTOK * KP45];
__device__ __align__(256) __nv_bfloat16 g_ah1 [NTOK * KP6];
__device__ __align__(256) __nv_bfloat16 g_wc1t[CH    * KP1];
__device__ __align__(256) __nv_bfloat16 g_wc2t[NPAD2 * KP2];
__device__ __align__(256) __nv_bfloat16 g_w1t [HIDDIM* KP45];
__device__ __align__(256) __nv_bfloat16 g_w3t [HIDDIM* KP45];
__device__ __align__(256) __nv_bfloat16 g_w2t [NPAD6 * KP6];

// ---------------- helpers ----------------
__device__ __forceinline__ uint32_t smem_u32(const void* p) {
    uint32_t a;
    asm("{ .reg .u64 t; cvta.to.shared.u64 t, %1; cvt.u32.u64 %0, t; }"
        : "=r"(a) : "l"(p));
    return a;
}
#define CPA16(sa, gp) asm volatile("cp.async.cg.shared.global [%0], [%1], 16;" ::"r"(sa),"l"(gp):"memory")
#define CPA_COMMIT()  asm volatile("cp.async.commit_group;" ::: "memory")
#define CPA_WAIT(n)   asm volatile("cp.async.wait_group %0;" ::"n"(n):"memory")

__device__ __forceinline__ void ldmx4(uint32_t* r, uint32_t addr) {
    asm volatile("ldmatrix.sync.aligned.m8n8.x4.shared.b16 {%0,%1,%2,%3}, [%4];"
        : "=r"(r[0]), "=r"(r[1]), "=r"(r[2]), "=r"(r[3]) : "r"(addr));
}
__device__ __forceinline__ void mma16816(float* c, const uint32_t* a,
                                         uint32_t b0, uint32_t b1) {
    asm volatile("mma.sync.aligned.m16n8k16.row.col.f32.bf16.bf16.f32 "
        "{%0,%1,%2,%3}, {%4,%5,%6,%7}, {%8,%9}, {%0,%1,%2,%3};"
        : "+f"(c[0]), "+f"(c[1]), "+f"(c[2]), "+f"(c[3])
        : "r"(a[0]), "r"(a[1]), "r"(a[2]), "r"(a[3]), "r"(b0), "r"(b1));
}

// ---------------- bf16x2 split ----------------
__device__ __forceinline__ void split2(float v, unsigned short& o0,
                                       unsigned short& o1) {
    __nv_bfloat16 b0 = __float2bfloat16_rn(v);
    float r = v - __bfloat162float(b0);
    __nv_bfloat16 b1 = __float2bfloat16_rn(r);
    o0 = *reinterpret_cast<unsigned short*>(&b0);
    o1 = *reinterpret_cast<unsigned short*>(&b1);
}

// ---------------- activation convert: [M,K] f32 -> [M,3K] planes [P0,P0,P1] ----------------
__global__ __launch_bounds__(256)
void convert_act(const float* __restrict__ src, __nv_bfloat16* __restrict__ dst,
                 int K, int total4)
{
    int i4 = blockIdx.x * 256 + threadIdx.x;
    if (i4 >= total4) return;
    long idx = (long)i4 * 4;
    int m = (int)(idx / K), k = (int)(idx % K);
    float4 v = *(const float4*)(src + idx);
    ushort4 p0, p1;
    split2(v.x, p0.x, p1.x);
    split2(v.y, p0.y, p1.y);
    split2(v.z, p0.z, p1.z);
    split2(v.w, p0.w, p1.w);
    long base = (long)m * (3L * K) + k;
    *(ushort4*)(dst + base)        = p0;
    *(ushort4*)(dst + base + K)    = p0;
    *(ushort4*)(dst + base + 2L*K) = p1;
}

// ---------------- weight convert+transpose: w[K,N] f32 -> [N,3K] planes [P0,P1,P0] ----------------
__global__ void convert_wT(const float* __restrict__ w, __nv_bfloat16* __restrict__ dst,
                           int K, int N)
{
    __shared__ float t[32][33];
    int n0 = blockIdx.x * 32, k0 = blockIdx.y * 32;
    int tx = threadIdx.x, ty = threadIdx.y;          // 32 x 8
#pragma unroll
    for (int r = 0; r < 4; r++)
        t[ty + r * 8][tx] = w[(long)(k0 + ty + r * 8) * N + n0 + tx];
    __syncthreads();
    unsigned short* d = (unsigned short*)dst;
#pragma unroll
    for (int r = 0; r < 4; r++) {
        int n = n0 + ty + r * 8;
        float v = t[tx][ty + r * 8];
        unsigned short b0, b1;
        split2(v, b0, b1);
        long base = (long)n * (3L * K) + k0 + tx;
        d[base]        = b0;
        d[base + K]    = b1;
        d[base + 2L*K] = b0;
    }
}

// ============ bf16 mma.sync GEMM: C[M,Nact] = epi(A[M,Kp] @ Bt[Npad,Kp]^T) ============
// EPI: 0=none, 1=+bias, 2=gelu(+bias), 3=silu(aux)*acc, 4=+aux
template <int EPI>
__global__ __launch_bounds__(256)
void mmagemm(int Kp, const __nv_bfloat16* __restrict__ A,
             const __nv_bfloat16* __restrict__ Bt,
             float* __restrict__ C, int Nact,
             const float* __restrict__ bias, const float* __restrict__ aux)
{
    constexpr int BM = 128, BN = 128, BK = 32;
    constexpr int RSTB = 80;                 // smem row stride bytes (64 data + 16 pad)
    constexpr int TILEB = 128 * RSTB;        // 10240 B per operand tile
    constexpr int STAGEB = 2 * TILEB;        // 20480 B per stage
    extern __shared__ char smc[];
    const uint32_t sb = smem_u32(smc);
    const int tid = threadIdx.x, lane = tid & 31, w = tid >> 5;
    const int wm = w >> 2, wn = w & 3;
    const int bm = blockIdx.y * BM, bn = blockIdx.x * BN;

    const __nv_bfloat16* Ag = A + (long)bm * Kp;
    const __nv_bfloat16* Bg = Bt + (long)bn * Kp;
    const int lrow = tid >> 2;               // 0..63
    const int lseg = tid & 3;                // 16B segment within 64B row

    const int KT = Kp / BK;

    float acc[4][4][4];
#pragma unroll
    for (int i = 0; i < 4; i++)
#pragma unroll
        for (int j = 0; j < 4; j++)
#pragma unroll
            for (int q = 0; q < 4; q++) acc[i][j][q] = 0.f;

    // ---- 3-stage cp.async pipeline ----
    auto load_stage = [&](int s, int kt) {
        uint32_t as = sb + s * STAGEB;
        uint32_t bs = as + TILEB;
        long ko = (long)kt * BK + lseg * 8;
#pragma unroll
        for (int h = 0; h < 2; h++) {
            int r = lrow + h * 64;
            CPA16(as + r * RSTB + lseg * 16, Ag + (long)r * Kp + ko);
            CPA16(bs + r * RSTB + lseg * 16, Bg + (long)r * Kp + ko);
        }
        CPA_COMMIT();
    };

    load_stage(0, 0);
    if (KT > 1) load_stage(1, 1);

    const int arow = lane & 15;
    const int acol = (lane >> 4) * 16;

    for (int kt = 0; kt < KT; kt++) {
        if (kt + 2 < KT) { load_stage((kt + 2) % 3, kt + 2); CPA_WAIT(2); }
        else if (kt + 1 < KT) CPA_WAIT(1);
        else CPA_WAIT(0);
        __syncthreads();

        const uint32_t as = sb + (kt % 3) * STAGEB;
        const uint32_t bs = as + TILEB;
#pragma unroll
        for (int kk = 0; kk < 2; kk++) {
            const int co = kk * 32 + acol;
            uint32_t af[4][4], bf[2][4];
#pragma unroll
            for (int mi = 0; mi < 4; mi++)
                ldmx4(af[mi], as + (wm * 64 + mi * 16 + arow) * RSTB + co);
#pragma unroll
            for (int nj = 0; nj < 2; nj++)
                ldmx4(bf[nj], bs + (wn * 32 + nj * 16 + arow) * RSTB + co);
#pragma unroll
            for (int mi = 0; mi < 4; mi++)
#pragma unroll
                for (int ni = 0; ni < 4; ni++)
                    mma16816(acc[mi][ni], af[mi],
                             bf[ni >> 1][ni & 1], bf[ni >> 1][(ni & 1) + 2]);
        }
        __syncthreads();
    }

    // ---- epilogue ----
#pragma unroll
    for (int mi = 0; mi < 4; mi++) {
#pragma unroll
        for (int ni = 0; ni < 4; ni++) {
            int col = bn + wn * 32 + ni * 8 + (lane & 3) * 2;
            if (col >= Nact) continue;
#pragma unroll
            for (int h = 0; h < 2; h++) {
                long row = bm + wm * 64 + mi * 16 + (lane >> 2) + h * 8;
                float v0 = acc[mi][ni][h * 2 + 0];
                float v1 = acc[mi][ni][h * 2 + 1];
                if (EPI == 1) { v0 += __ldg(bias + col); v1 += __ldg(bias + col + 1); }
                else if (EPI == 2) {
                    v0 += __ldg(bias + col); v1 += __ldg(bias + col + 1);
                    v0 = 0.5f * v0 * (1.0f + erff(v0 * 0.70710678118654752f));
                    v1 = 0.5f * v1 * (1.0f + erff(v1 * 0.70710678118654752f));
                } else if (EPI == 3) {
                    float2 s = *(const float2*)(aux + row * Nact + col);
                    v0 = (s.x / (1.0f + expf(-s.x))) * v0;
                    v1 = (s.y / (1.0f + expf(-s.y))) * v1;
                } else if (EPI == 4) {
                    float2 a = *(const float2*)(aux + row * Nact + col);
                    v0 += a.x; v1 += a.y;
                }
                *(float2*)(C + row * Nact + col) = make_float2(v0, v1);
            }
        }
    }
}

// ---------------- build gi = rmsnorm(concat(x, ctx, pos_emb)) ----------------
__global__ __launch_bounds__(256)
void build_gi_kernel(const float* __restrict__ x,
                     const int* __restrict__ positions,
                     const float* __restrict__ pos_table,
                     const float* __restrict__ normw)
{
    int row = blockIdx.x;
    __shared__ float vec[DGDIM];
    __shared__ float red[256];
    int tid = threadIdx.x;
    const float* xr = x + (long)row * HDIM;
    const float* pr = pos_table + (long)positions[row] * POSD;
    float ss = 0.f;
    for (int i = tid; i < DGDIM; i += 256) {
        float v;
        if (i < HDIM) v = xr[i];
        else if (i < HDIM + CTXD) v = g_ctx[(long)row * CTXD + (i - HDIM)];
        else v = pr[i - HDIM - CTXD];
        vec[i] = v;
        ss += v * v;
    }
    red[tid] = ss;
    __syncthreads();
    for (int s = 128; s > 0; s >>= 1) {
        if (tid < s) red[tid] += red[tid + s];
        __syncthreads();
    }
    float scale = rsqrtf(red[0] / (float)DGDIM + 1e-6f);
    for (int i = tid; i < DGDIM; i += 256)
        g_gi[(long)row * DGDIM + i] = vec[i] * scale * normw[i];
}

// ---------------- router ----------------
__global__ __launch_bounds__(256)
void router_kernel(const float* __restrict__ projw,
                   const float* __restrict__ tptr,
                   float* __restrict__ out)
{
    int row = blockIdx.x * 8 + (threadIdx.x >> 5);
    int lane = threadIdx.x & 31;
    if (row >= NTOK) return;
    const float* h = g_h + (long)row * DGDIM;
    float acc[NEXP];
#pragma unroll
    for (int e = 0; e < NEXP; e++) acc[e] = 0.f;
    for (int i = lane; i < DGDIM; i += 32) {
        float hv = h[i];
        const float4* p = (const float4*)(projw + (long)i * NEXP);
        float4 w0 = p[0], w1 = p[1];
        acc[0] += hv * w0.x; acc[1] += hv * w0.y;
        acc[2] += hv * w0.z; acc[3] += hv * w0.w;
        acc[4] += hv * w1.x; acc[5] += hv * w1.y;
        acc[6] += hv * w1.z; acc[7] += hv * w1.w;
    }
#pragma unroll
    for (int e = 0; e < NEXP; e++)
#pragma unroll
        for (int o = 16; o > 0; o >>= 1)
            acc[e] += __shfl_xor_sync(0xFFFFFFFFu, acc[e], o);

    if (lane == 0) {
        float t = fmaxf(*tptr, 0.3f);
        float l[NEXP], m = -1e30f;
#pragma unroll
        for (int e = 0; e < NEXP; e++) { l[e] = acc[e] / t; m = fmaxf(m, l[e]); }
        float s = 0.f;
#pragma unroll
        for (int e = 0; e < NEXP; e++) { l[e] = expf(l[e] - m); s += l[e]; }
        float inv = 1.0f / s;
#pragma unroll
        for (int e = 0; e < NEXP; e++) {
            l[e] *= inv;
            g_scores[(long)row * NEXP + e] = l[e];
        }
        int i1 = 0;
#pragma unroll
        for (int e = 1; e < NEXP; e++) if (l[e] > l[i1]) i1 = e;
        int i2 = (i1 == 0) ? 1 : 0;
#pragma unroll
        for (int e = 0; e < NEXP; e++)
            if (e != i1 && e != i2 && l[e] > l[i2]) i2 = e;

        int idx2[2] = {i1, i2};
#pragma unroll
        for (int k = 0; k < 2; k++) {
            int fi = row * 2 + k;
            float wv = l[idx2[k]];
            out[OFF_IDX + fi] = (float)idx2[k];
            out[OFF_SCORE + fi] = wv;
            g_expert_flat[fi] = idx2[k];
            unsigned int bits = __float_as_uint(wv);
            g_keys[fi] = ((unsigned long long)(0xFFFFFFFFu - bits) << 32) |
                         (unsigned long long)(unsigned int)fi;
        }
    }
}

// ---------------- single-block bitonic sort + capacity dispatch ----------------
__global__ __launch_bounds__(1024, 1)
void sort_dispatch_kernel(float* __restrict__ out)
{
    extern __shared__ unsigned long long keys[];
    const int tid = threadIdx.x;
    for (int i = tid; i < NKENT; i += 1024) keys[i] = g_keys[i];
    __syncthreads();
    for (int k = 2; k <= NKENT; k <<= 1) {
        for (int j = k >> 1; j > 0; j >>= 1) {
            for (int i = tid; i < NKENT; i += 1024) {
                int ixj = i ^ j;
                if (ixj > i) {
                    bool up = ((i & k) == 0);
                    unsigned long long a = keys[i], b = keys[ixj];
                    if ((a > b) == up) { keys[i] = b; keys[ixj] = a; }
                }
            }
            __syncthreads();
        }
    }
    int warp = tid >> 5, lane = tid & 31;
    if (warp < NEXP) {
        int c = 0;
        for (int base = 0; base < NKENT; base += 32) {
            unsigned long long kk = keys[base + lane];
            int idx = (int)(kk & 0xFFFFFFFFu);
            int e = g_expert_flat[idx];
            unsigned int mask = __ballot_sync(0xFFFFFFFFu, e == warp);
            if (e == warp) {
                int rank = c + __popc(mask & ((1u << lane) - 1u));
                bool ok = rank < CAP;
                g_assigned[idx] = ok ? 1 : 0;
                out[OFF_MASK + idx] = ok ? 1.0f : 0.0f;
                out[OFF_POS + idx] = ok ? (float)rank : 0.0f;
            }
            c += __popc(mask);
        }
        if (lane == 0) {
            int cnt = c < CAP ? c : CAP;
            g_cnt[warp] = cnt;
            out[OFF_CNT + warp] = (float)cnt;
        }
    }
    __syncthreads();
    for (int n = tid; n < NTOK; n += 1024)
        out[OFF_OVER + n] =
            (g_assigned[2 * n] | g_assigned[2 * n + 1]) ? 0.0f : 1.0f;
}

// ---------------- next_context mean ----------------
__global__ __launch_bounds__(256)
void next_ctx_kernel(const int* __restrict__ positions,
                     const float* __restrict__ pos_table,
                     float* __restrict__ out)
{
    int j = blockIdx.x % (CTXD + POSD);
    int b = blockIdx.x / (CTXD + POSD);
    __shared__ float red[256];
    float s = 0.f;
    for (int t = threadIdx.x; t < SEQ; t += 256) {
        int row = b * SEQ + t;
        float v = (j < CTXD) ? g_ctx[(long)row * CTXD + j]
                             : pos_table[(long)positions[row] * POSD + (j - CTXD)];
        s += v;
    }
    red[threadIdx.x] = s;
    __syncthreads();
    for (int st = 128; st > 0; st >>= 1) {
        if (threadIdx.x < st) red[threadIdx.x] += red[threadIdx.x + st];
        __syncthreads();
    }
    if (threadIdx.x == 0)
        out[OFF_NEXT + b * (CTXD + POSD) + j] = red[0] / (float)SEQ;
}

// ---------------- aux loss ----------------
__global__ __launch_bounds__(256)
void aux_kernel(float* __restrict__ out)
{
    __shared__ float sh[256 * NEXP];
    int tid = threadIdx.x;
    float acc[NEXP];
#pragma unroll
    for (int e = 0; e < NEXP; e++) acc[e] = 0.f;
    for (int r = tid; r < NTOK; r += 256)
#pragma unroll
        for (int e = 0; e < NEXP; e++) acc[e] += g_scores[(long)r * NEXP + e];
#pragma unroll
    for (int e = 0; e < NEXP; e++) sh[tid * NEXP + e] = acc[e];
    __syncthreads();
    for (int s = 128; s > 0; s >>= 1) {
        if (tid < s)
#pragma unroll
            for (int e = 0; e < NEXP; e++)
                sh[tid * NEXP + e] += sh[(tid + s) * NEXP + e];
        __syncthreads();
    }
    if (tid == 0) {
        float a = 0.f;
        for (int e = 0; e < NEXP; e++) {
            float me = sh[e] / (float)NTOK;
            float ce = (float)g_cnt[e] / (float)NTOK;
            a += me * ce;
        }
        out[OFF_AUX] = 0.01f * (float)NEXP * a;
    }
}

// ---------------- launch ----------------
extern "C" void kernel_launch(void* const* d_in, const int* in_sizes, int n_in,
                              void* d_out, int out_size)
{
    const float* x        = (const float*)d_in[0];
    const int*   positions= (const int*)d_in[1];
    const float* w_c1     = (const float*)d_in[2];
    const float* b_c1     = (const float*)d_in[3];
    const float* w_c2     = (const float*)d_in[4];
    const float* b_c2     = (const float*)d_in[5];
    const float* norm_w   = (const float*)d_in[6];
    const float* mlp_w1   = (const float*)d_in[7];
    const float* mlp_w3   = (const float*)d_in[8];
    const float* mlp_w2   = (const float*)d_in[9];
    const float* proj_w   = (const float*)d_in[10];
    const float* pos_table= (const float*)d_in[11];
    const float* temp     = (const float*)d_in[12];
    float* out = (float*)d_out;

    float *p_hidden, *p_ctx, *p_gi, *p_s1, *p_h1, *p_h;
    __nv_bfloat16 *p_ax, *p_ah, *p_agi, *p_ah1;
    __nv_bfloat16 *p_wc1t, *p_wc2t, *p_w1t, *p_w3t, *p_w2t;
    cudaGetSymbolAddress((void**)&p_hidden, g_hidden);
    cudaGetSymbolAddress((void**)&p_ctx,    g_ctx);
    cudaGetSymbolAddress((void**)&p_gi,     g_gi);
    cudaGetSymbolAddress((void**)&p_s1,     g_s1);
    cudaGetSymbolAddress((void**)&p_h1,     g_h1);
    cudaGetSymbolAddress((void**)&p_h,      g_h);
    cudaGetSymbolAddress((void**)&p_ax,     g_ax);
    cudaGetSymbolAddress((void**)&p_ah,     g_ah);
    cudaGetSymbolAddress((void**)&p_agi,    g_agi);
    cudaGetSymbolAddress((void**)&p_ah1,    g_ah1);
    cudaGetSymbolAddress((void**)&p_wc1t,   g_wc1t);
    cudaGetSymbolAddress((void**)&p_wc2t,   g_wc2t);
    cudaGetSymbolAddress((void**)&p_w1t,    g_w1t);
    cudaGetSymbolAddress((void**)&p_w3t,    g_w3t);
    cudaGetSymbolAddress((void**)&p_w2t,    g_w2t);

    const int GSM = 61440;   // 3 stages x 20480
    cudaFuncSetAttribute(mmagemm<0>, cudaFuncAttributeMaxDynamicSharedMemorySize, GSM);
    cudaFuncSetAttribute(mmagemm<1>, cudaFuncAttributeMaxDynamicSharedMemorySize, GSM);
    cudaFuncSetAttribute(mmagemm<2>, cudaFuncAttributeMaxDynamicSharedMemorySize, GSM);
    cudaFuncSetAttribute(mmagemm<3>, cudaFuncAttributeMaxDynamicSharedMemorySize, GSM);
    cudaFuncSetAttribute(mmagemm<4>, cudaFuncAttributeMaxDynamicSharedMemorySize, GSM);
    cudaFuncSetAttribute(sort_dispatch_kernel,
                         cudaFuncAttributeMaxDynamicSharedMemorySize,
                         NKENT * (int)sizeof(unsigned long long));

    // zero padded weight buffers (pad rows must multiply to 0)
    cudaMemsetAsync(p_wc2t, 0, (size_t)NPAD2 * KP2 * sizeof(__nv_bfloat16));
    cudaMemsetAsync(p_w2t,  0, (size_t)NPAD6 * KP6 * sizeof(__nv_bfloat16));

    // weight converts
    convert_wT<<<dim3(CH / 32, HDIM / 32),      dim3(32, 8)>>>(w_c1,   p_wc1t, HDIM,   CH);
    convert_wT<<<dim3(CTXD / 32, CH / 32),      dim3(32, 8)>>>(w_c2,   p_wc2t, CH,     CTXD);
    convert_wT<<<dim3(HIDDIM / 32, DGDIM / 32), dim3(32, 8)>>>(mlp_w1, p_w1t,  DGDIM,  HIDDIM);
    convert_wT<<<dim3(HIDDIM / 32, DGDIM / 32), dim3(32, 8)>>>(mlp_w3, p_w3t,  DGDIM,  HIDDIM);
    convert_wT<<<dim3(DGDIM / 32, HIDDIM / 32), dim3(32, 8)>>>(mlp_w2, p_w2t,  HIDDIM, DGDIM);
    // x split
    convert_act<<<(NTOK * HDIM / 4 + 255) / 256, 256>>>(x, p_ax, HDIM, NTOK * HDIM / 4);

    // 1. hidden = gelu(x @ w_c1 + b_c1)
    mmagemm<2><<<dim3(CH / 128, NTOK / 128), 256, GSM>>>(
        KP1, p_ax, p_wc1t, p_hidden, CH, b_c1, nullptr);
    convert_act<<<(NTOK * CH / 4 + 255) / 256, 256>>>(p_hidden, p_ah, CH, NTOK * CH / 4);
    // 2. ctx = hidden @ w_c2 + b_c2
    mmagemm<1><<<dim3(NPAD2 / 128, NTOK / 128), 256, GSM>>>(
        KP2, p_ah, p_wc2t, p_ctx, CTXD, b_c2, nullptr);
    // 3. gi = rmsnorm(concat(x, ctx, pos_emb))
    build_gi_kernel<<<NTOK, 256>>>(x, positions, pos_table, norm_w);
    convert_act<<<(NTOK * DGDIM / 4 + 255) / 256, 256>>>(p_gi, p_agi, DGDIM, NTOK * DGDIM / 4);
    // 4. s1 = gi @ mlp_w1
    mmagemm<0><<<dim3(HIDDIM / 128, NTOK / 128), 256, GSM>>>(
        KP45, p_agi, p_w1t, p_s1, HIDDIM, nullptr, nullptr);
    // 5. h1 = silu(s1) * (gi @ mlp_w3)
    mmagemm<3><<<dim3(HIDDIM / 128, NTOK / 128), 256, GSM>>>(
        KP45, p_agi, p_w3t, p_h1, HIDDIM, nullptr, p_s1);
    convert_act<<<(NTOK * HIDDIM / 4 + 255) / 256, 256>>>(p_h1, p_ah1, HIDDIM, NTOK * HIDDIM / 4);
    // 6. h = h1 @ mlp_w2 + gi
    mmagemm<4><<<dim3(NPAD6 / 128, NTOK / 128), 256, GSM>>>(
        KP6, p_ah1, p_w2t, p_h, DGDIM, nullptr, p_gi);
    // 7-10. router, dispatch, next_context, aux
    router_kernel<<<NTOK / 8, 256>>>(proj_w, temp, out);
    sort_dispatch_kernel<<<1, 1024, NKENT * sizeof(unsigned long long)>>>(out);
    next_ctx_kernel<<<BATCH * (CTXD + POSD), 256>>>(positions, pos_table, out);
    aux_kernel<<<1, 256>>>(out);
}